// round 12
// baseline (speedup 1.0000x reference)
#include <cuda_runtime.h>

// BatchDelayProcessor: lag-D feedback delay line.
//   c_k = x_k + FB * c_{k-1}         (carry per chain, c_{-1} = 0)
//   out_k = (1-MIX) * x_k + MIX * c_{k-1}
// Each (b, j) with j in [0, D) is an independent length-NBLK chain:
// one thread owns one float2 chain, fully unrolled over the 20 k-blocks.
//
// FINAL. Roofline: steady-state graph-replay traffic is compulsory 226 MB
// (113 MB input re-read — dirty output evicts x from the 126 MB L2, and all
// L2 replacement hints are inert at the default carveout — plus 113 MB
// output writeback). Achieved mixed-R/W HBM ceiling ~5.7 TB/s => ~39.4us.
// Probes ruled out: evict_last/evict_first policies, .cs/.wt stores,
// front-batched MLP, smem-staged 128-bit accesses, persistent single-wave
// grid, block-size sweep. block=512 measured the best profile
// (DRAM 69.2%, 5482 GB/s) and ties the fastest e2e.

#define D_SAMP   22050
#define T_LEN    441000
#define B_SZ     64
#define NBLK     20          // T_LEN / D_SAMP
#define FB       0.3f
#define MIXC     0.5f

// float2 vectorization: D_SAMP % 2 == 0
#define HD       (D_SAMP / 2)            // 11025 float2 chains per batch row
#define NCHAINS  (B_SZ * HD)             // 705600 (fits in int)

#define CTA_THREADS 512

__global__ __launch_bounds__(CTA_THREADS) void delay_kernel(const float* __restrict__ x,
                                                            float* __restrict__ out) {
    int idx = blockIdx.x * CTA_THREADS + threadIdx.x;
    if (idx >= NCHAINS) return;

    int b = idx / HD;
    int j = (idx - b * HD) * 2;

    const char* xbase = (const char*)(x + (size_t)b * T_LEN + j);
    char*       obase = (char*)(out + (size_t)b * T_LEN + j);

    float2 c;
    c.x = 0.0f;
    c.y = 0.0f;

    const size_t blk_stride = (size_t)D_SAMP * sizeof(float);  // 88200 B

#pragma unroll
    for (int k = 0; k < NBLK; k++) {
        float2 xv = *reinterpret_cast<const float2*>(xbase + (size_t)k * blk_stride);
        float2 o;
        // out = x*(1-MIX) + c*MIX
        o.x = fmaf(c.x, MIXC, xv.x * (1.0f - MIXC));
        o.y = fmaf(c.y, MIXC, xv.y * (1.0f - MIXC));
        *reinterpret_cast<float2*>(obase + (size_t)k * blk_stride) = o;
        // c = x + FB*c
        c.x = fmaf(c.x, FB, xv.x);
        c.y = fmaf(c.y, FB, xv.y);
    }
}

extern "C" void kernel_launch(void* const* d_in, const int* in_sizes, int n_in,
                              void* d_out, int out_size) {
    const float* x = (const float*)d_in[0];
    float* out = (float*)d_out;

    const int blocks = (NCHAINS + CTA_THREADS - 1) / CTA_THREADS;  // 1379
    delay_kernel<<<blocks, CTA_THREADS>>>(x, out);
}